// round 12
// baseline (speedup 1.0000x reference)
#include <cuda_runtime.h>
#include <cuda_bf16.h>

#define Bn 8
#define Dn 1024
#define Gn 32
#define Kn 64
#define NPn 1024
#define NTILE 128     // n-rows per work unit
#define KC 32         // k-chunk (pipeline stage = half a group)
#define GRID 592      // 148 SMs * 4 CTA/SM -> exactly one wave

// Scratch (device globals; no allocation allowed)
__device__ float g_xzT[(size_t)Bn * Dn * NPn];   // 32 MB: z transposed [b][d][n]
__device__ float g_cw[Bn * Gn * Kn];             // folded coeff*mask*weight
__device__ int   g_items[Bn * Gn];               // packed (b<<8)|g, valid groups
__device__ int   g_nitems;

// packed dual-fp32 FMA (Blackwell f32x2; PTX-only, ptxas won't auto-fuse)
#define FMA2(acc, m, r) \
    asm("fma.rn.f32x2 %0, %1, %2, %0;" : "+l"(acc) : "l"(m), "l"(r))

#define CP_ASYNC16(dst_s32, src_g) \
    asm volatile("cp.async.cg.shared.global [%0], [%1], 16;" \
                 :: "r"(dst_s32), "l"(src_g))
#define CP_COMMIT() asm volatile("cp.async.commit_group;")

// ---------------------------------------------------------------------------
// Kernel 1 (prep): lean tiled transpose; blocks (0,0,b) also build cw
// (exp2f only — fp32 MUFU), out zeroing, work list.
// ---------------------------------------------------------------------------
__global__ void prep_kernel(const float* __restrict__ x,
                            const float* __restrict__ xopt,
                            const int*   __restrict__ gc,
                            const void*  __restrict__ vm,
                            const float* __restrict__ w,
                            float*       __restrict__ out)
{
    __shared__ float t[32][33];
    int b  = blockIdx.z;
    int n0 = blockIdx.x * 32;
    int d0 = blockIdx.y * 32;
    int tx = threadIdx.x, ty = threadIdx.y;

    #pragma unroll
    for (int j = ty; j < 32; j += 8) {
        int n = n0 + j, d = d0 + tx;
        t[j][tx] = x[((size_t)b * NPn + n) * Dn + d] - xopt[b * Dn + d];
    }
    __syncthreads();
    #pragma unroll
    for (int j = ty; j < 32; j += 8) {
        int d = d0 + j, n = n0 + tx;
        g_xzT[((size_t)b * Dn + d) * NPn + n] = t[tx][j];
    }

    if (blockIdx.x == 0 && blockIdx.y == 0) {
        int tid = ty * 32 + tx;

        // valid_mask storage width (uniform, 16 L2 loads)
        int mode4 = 1;
        #pragma unroll
        for (int i = 0; i < 16; ++i) {
            unsigned int v = __ldg((const unsigned int*)vm + i);
            if (v != 0u && v != 1u && v != 0x3F800000u) mode4 = 0;
        }

        int gcb = gc[b];
        for (int i = tid; i < Gn * Kn; i += 256) {
            int g = i >> 6, k = i & 63;
            int gi = b * Gn * Kn + i;
            bool m;
            if (mode4) m = (((const unsigned int*)vm)[gi] != 0u);
            else       m = (((const unsigned char*)vm)[gi] != 0);
            float cf = exp2f((float)k * (19.931568569324174f / 63.0f));
            float wv = (g < gcb) ? w[b * Gn + g] : 0.0f;
            g_cw[gi] = m ? cf * wv : 0.0f;
        }
        for (int i = tid; i < NPn; i += 256) out[b * NPn + i] = 0.0f;
        if (b == 0 && tid == 0) {
            int mcnt = 0;
            for (int bb = 0; bb < Bn; ++bb) {
                int c = gc[bb];
                for (int g = 0; g < c; ++g) g_items[mcnt++] = (bb << 8) | g;
            }
            g_nitems = mcnt;
        }
    }
}

// ---------------------------------------------------------------------------
// Kernel 2: fitness. Grid GRID=592 (one wave @ 4 CTA/SM), block 256.
// CTA c processes units c, c+GRID, ... ; unit = item*8 + tile.
// Stage = 32-k half of one unit; double-buffered, ONE barrier per stage.
// Thread tile 4n x 8l (1 LDS.128 z + 2 bcast LDS.128 R + MOV dup + 16 FMA2).
// NEW vs R11:
//   - gather column idx prefetched TWO stages ahead (ISSUE has no exposed
//     LDG->cp.async dependency after the barrier)
//   - cw staged into smem at unit start (h==0), consumed a full stage later
// Dynamic smem: Rs (16KB) | zs[2] (32KB) | cw_s (256B).
// ---------------------------------------------------------------------------
__global__ __launch_bounds__(256, 4) void fitness_kernel(
    const float* __restrict__ R,
    const int*   __restrict__ gidx,
    float*       __restrict__ out)
{
    extern __shared__ char sm[];
    float* Rs   = (float*)sm;                    // 16 KB
    float* zs   = (float*)(sm + 16384);          // 2 * 16 KB
    float* cw_s = (float*)(sm + 16384 + 32768);  // 64 floats

    int tid = threadIdx.x;
    int cta = blockIdx.x;
    int nt  = tid & 31;
    int lt  = tid >> 5;

    int nunits = 8 * g_nitems;
    int mu = (cta < nunits) ? ((nunits - 1 - cta) / GRID + 1) : 0;
    if (mu == 0) return;
    int ts = 2 * mu;

    for (int i = tid; i < Kn * Kn; i += 256) Rs[i] = R[i];
    __syncthreads();   // Rs visible to all warps before any use

    // gather: thread owns k_local = tid>>3 (0..31), 16B n-chunks (tid&7)+8j
    int kq = tid >> 3;
    int nq = tid & 7;
    unsigned int zb0 = (unsigned int)__cvta_generic_to_shared(zs);

    // idx gmem address for stage s (this thread's column index)
    #define IDX_ADDR(s) \
        (gidx + (((g_items[(cta + ((s) >> 1) * GRID) >> 3]) >> 8) * Gn + \
                 ((g_items[(cta + ((s) >> 1) * GRID) >> 3]) & 255)) * Kn + \
                ((s) & 1) * KC + kq)

    // issue gather for stage s using prefetched column col
    #define ISSUE(s, col)                                                      \
    {                                                                          \
        int u_  = cta + ((s) >> 1) * GRID;                                     \
        int it_ = g_items[u_ >> 3];                                            \
        int b_  = it_ >> 8, n0_ = (u_ & 7) * NTILE;                            \
        const float* src_ = &g_xzT[((size_t)(b_ * Dn + (col))) * NPn + n0_];   \
        unsigned int db_ = zb0 + ((s) & 1) * 16384 + kq * (NTILE * 4);         \
        _Pragma("unroll")                                                      \
        for (int jj = 0; jj < 4; ++jj) {                                       \
            int nof_ = (nq + 8 * jj) * 4;                                      \
            CP_ASYNC16(db_ + nof_ * 4, src_ + nof_);                           \
        }                                                                      \
        CP_COMMIT();                                                           \
    }

    unsigned long long acc[4][4];   // [n][l-pair]
    int uitem = 0, un0 = 0;

    int colA = __ldg(IDX_ADDR(0));
    ISSUE(0, colA);
    int colN = (ts > 1) ? __ldg(IDX_ADDR(1)) : 0;   // col for next stage

    for (int j = 0; j < ts; ++j) {
        int h = j & 1;

        asm volatile("cp.async.wait_group 0;");   // stage j landed
        __syncthreads();   // data visible; all warps past compute(j-1)
                           // -> buffer (j+1)&1 free; cw_s from h==0 visible
        if (j + 1 < ts) ISSUE(j + 1, colN);       // no LDG dependency here
        if (j + 2 < ts) colN = __ldg(IDX_ADDR(j + 2));  // lands during j, j+1

        if (h == 0) {
            // new unit: decode, stage cw into smem (consumed at h==1, a full
            // stage away -> latency fully covered), reset accumulators
            int u = cta + (j >> 1) * GRID;
            uitem = u >> 3;
            un0   = (u & 7) * NTILE;
            if (tid < Kn) {
                int it = g_items[uitem];
                cw_s[tid] = __ldg(g_cw + ((it >> 8) * Gn + (it & 255)) * Kn + tid);
            }
            #pragma unroll
            for (int i = 0; i < 4; ++i)
                #pragma unroll
                for (int jj = 0; jj < 4; ++jj) acc[i][jj] = 0ull;
        }

        const float* zb   = zs + (j & 1) * (KC * NTILE);
        const float* rrow = &Rs[h * KC * Kn + lt * 8];

        #pragma unroll 8
        for (int kl = 0; kl < KC; ++kl) {
            float4 z4 = *(const float4*)&zb[kl * NTILE + nt * 4];
            const ulonglong2* rp = (const ulonglong2*)&rrow[kl * Kn];
            ulonglong2 ra = rp[0];
            ulonglong2 rb = rp[1];
            unsigned long long z2[4];
            asm("mov.b64 %0, {%1, %1};" : "=l"(z2[0]) : "f"(z4.x));
            asm("mov.b64 %0, {%1, %1};" : "=l"(z2[1]) : "f"(z4.y));
            asm("mov.b64 %0, {%1, %1};" : "=l"(z2[2]) : "f"(z4.z));
            asm("mov.b64 %0, {%1, %1};" : "=l"(z2[3]) : "f"(z4.w));
            #pragma unroll
            for (int i = 0; i < 4; ++i) {
                FMA2(acc[i][0], z2[i], ra.x);
                FMA2(acc[i][1], z2[i], ra.y);
                FMA2(acc[i][2], z2[i], rb.x);
                FMA2(acc[i][3], z2[i], rb.y);
            }
        }

        if (h == 1) {
            // unit done: cw from smem (staged a stage ago), square-fold,
            // reduce straight to gmem (REDG)
            int bb = g_items[uitem] >> 8;
            float cw_r[8];
            #pragma unroll
            for (int jj = 0; jj < 8; ++jj) cw_r[jj] = cw_s[lt * 8 + jj];

            #pragma unroll
            for (int i = 0; i < 4; ++i) {
                float s0 = 0.0f;
                #pragma unroll
                for (int jj = 0; jj < 4; ++jj) {
                    float lo = __uint_as_float((unsigned int)(acc[i][jj] & 0xFFFFFFFFull));
                    float hi = __uint_as_float((unsigned int)(acc[i][jj] >> 32));
                    s0 += cw_r[2 * jj] * lo * lo + cw_r[2 * jj + 1] * hi * hi;
                }
                atomicAdd(&out[bb * NPn + un0 + nt * 4 + i], s0);
            }
        }
    }
    #undef ISSUE
    #undef IDX_ADDR
}

// ---------------------------------------------------------------------------
// kernel_launch
// Inputs (metadata order): x, weights, xopt, R, group_indices, valid_mask,
//                          group_counts
// ---------------------------------------------------------------------------
extern "C" void kernel_launch(void* const* d_in, const int* in_sizes, int n_in,
                              void* d_out, int out_size)
{
    const float* x      = (const float*)d_in[0];
    const float* w      = (const float*)d_in[1];
    const float* xopt   = (const float*)d_in[2];
    const float* R      = (const float*)d_in[3];
    const int*   gidx   = (const int*)d_in[4];
    const void*  vmask  = (const void*)d_in[5];
    const int*   gc     = (const int*)d_in[6];
    float*       out    = (float*)d_out;

    const int smem_bytes = 16384 + 32768 + 256;
    cudaFuncSetAttribute(fitness_kernel,
                         cudaFuncAttributeMaxDynamicSharedMemorySize, smem_bytes);

    dim3 tg(NPn / 32, Dn / 32, Bn);
    prep_kernel<<<tg, dim3(32, 8)>>>(x, xopt, gc, vmask, w, out);

    fitness_kernel<<<GRID, 256, smem_bytes>>>(R, gidx, out);
}

// round 14
// speedup vs baseline: 1.7873x; 1.7873x over previous
#include <cuda_runtime.h>
#include <cuda_bf16.h>

#define Bn 8
#define Dn 1024
#define Gn 32
#define Kn 64
#define NPn 1024
#define NTILE 128
#define GRID 592      // 148 SMs * 4 CTA/SM, one wave

// Scratch (device globals; no allocation allowed)
__device__ float        g_xzT[(size_t)Bn * Dn * NPn];  // z transposed [b][d][n]
__device__ float        g_cw[Bn * Gn * Kn];            // coeff*mask*weight
__device__ unsigned int g_RT[2 * 2048];                // R^T bf16 hi|lo, SW128-preswizzled
__device__ int          g_items[Bn * Gn];
__device__ int          g_nitems;

#define SWZ(o) ((o) ^ (((o) >> 3) & 0x70))

// pack two f32 -> bf16x2 (lo half = first arg), round-to-nearest
#define CVT2(res, lo, hi) \
    asm("cvt.rn.bf16x2.f32 %0, %1, %2;" : "=r"(res) : "f"(hi), "f"(lo))

#define CP_ASYNC16(dst_s32, src_g) \
    asm volatile("cp.async.cg.shared.global [%0], [%1], 16;" \
                 :: "r"(dst_s32), "l"(src_g))
#define CP_COMMIT() asm volatile("cp.async.commit_group;")
#define CP_WAIT0()  asm volatile("cp.async.wait_group 0;")

__device__ __forceinline__ unsigned int smem_u32(const void* p) {
    unsigned int a;
    asm("{ .reg .u64 t; cvta.to.shared.u64 t, %1; cvt.u32.u64 %0, t; }"
        : "=r"(a) : "l"(p));
    return a;
}

#define LDSM4(r, addr) \
    asm volatile("ldmatrix.sync.aligned.m8n8.x4.shared.b16 {%0,%1,%2,%3}, [%4];" \
        : "=r"((r)[0]), "=r"((r)[1]), "=r"((r)[2]), "=r"((r)[3]) : "r"(addr))
#define LDSM2(r, addr) \
    asm volatile("ldmatrix.sync.aligned.m8n8.x2.shared.b16 {%0,%1}, [%2];" \
        : "=r"((r)[0]), "=r"((r)[1]) : "r"(addr))

#define MMA16816(d, a, b) \
    asm volatile("mma.sync.aligned.m16n8k16.row.col.f32.bf16.bf16.f32 " \
        "{%0,%1,%2,%3}, {%4,%5,%6,%7}, {%8,%9}, {%0,%1,%2,%3};" \
        : "+f"((d)[0]), "+f"((d)[1]), "+f"((d)[2]), "+f"((d)[3]) \
        : "r"((a)[0]), "r"((a)[1]), "r"((a)[2]), "r"((a)[3]), \
          "r"((b)[0]), "r"((b)[1]))

// smem layout (dynamic, region bases 1024-aligned for the swizzle)
#define SA1   0         // A z1: 128 x 64 bf16 (16 KB)
#define SA2   16384     // A z2
#define SB1   32768     // B r1: 64 x 64 bf16 (8 KB)
#define SB2   40960     // B r2
#define SIDX  49152     // 64 ints
#define SCW   49408     // 64 floats
#define SMEMB 49664

// ---------------------------------------------------------------------------
// Kernel 1 (prep): transpose + cw + work list + R^T bf16 split (pre-swizzled)
// ---------------------------------------------------------------------------
__global__ void prep_kernel(const float* __restrict__ x,
                            const float* __restrict__ xopt,
                            const int*   __restrict__ gc,
                            const void*  __restrict__ vm,
                            const float* __restrict__ w,
                            const float* __restrict__ R,
                            float*       __restrict__ out)
{
    __shared__ float t[32][33];
    int b  = blockIdx.z;
    int n0 = blockIdx.x * 32;
    int d0 = blockIdx.y * 32;
    int tx = threadIdx.x, ty = threadIdx.y;

    #pragma unroll
    for (int j = ty; j < 32; j += 8) {
        int n = n0 + j, d = d0 + tx;
        t[j][tx] = x[((size_t)b * NPn + n) * Dn + d] - xopt[b * Dn + d];
    }
    __syncthreads();
    #pragma unroll
    for (int j = ty; j < 32; j += 8) {
        int d = d0 + j, n = n0 + tx;
        g_xzT[((size_t)b * Dn + d) * NPn + n] = t[tx][j];
    }

    if (blockIdx.x == 0 && blockIdx.y == 0) {
        int tid = ty * 32 + tx;
        int mode4 = 1;
        #pragma unroll
        for (int i = 0; i < 16; ++i) {
            unsigned int v = __ldg((const unsigned int*)vm + i);
            if (v != 0u && v != 1u && v != 0x3F800000u) mode4 = 0;
        }
        int gcb = gc[b];
        for (int i = tid; i < Gn * Kn; i += 256) {
            int g = i >> 6, k = i & 63;
            int gi = b * Gn * Kn + i;
            bool m;
            if (mode4) m = (((const unsigned int*)vm)[gi] != 0u);
            else       m = (((const unsigned char*)vm)[gi] != 0);
            float cf = exp2f((float)k * (19.931568569324174f / 63.0f));
            float wv = (g < gcb) ? w[b * Gn + g] : 0.0f;
            g_cw[gi] = m ? cf * wv : 0.0f;
        }
        for (int i = tid; i < NPn; i += 256) out[b * NPn + i] = 0.0f;

        if (b == 0) {
            if (tid == 0) {
                int mcnt = 0;
                for (int bb = 0; bb < Bn; ++bb) {
                    int c = gc[bb];
                    for (int g = 0; g < c; ++g) g_items[mcnt++] = (bb << 8) | g;
                }
                g_nitems = mcnt;
            }
            // R^T bf16 hi/lo split, SW128-pre-swizzled rows of 128 B (row = l)
            for (int i = tid; i < 2048; i += 256) {
                int l = i >> 5, p = i & 31, k0 = 2 * p;
                float v0 = R[k0 * Kn + l];
                float v1 = R[(k0 + 1) * Kn + l];
                unsigned int r1p; CVT2(r1p, v0, v1);
                float v0r = v0 - __uint_as_float(r1p << 16);
                float v1r = v1 - __uint_as_float(r1p & 0xffff0000u);
                unsigned int r2p; CVT2(r2p, v0r, v1r);
                int off = l * 128 + 4 * p;
                int sw  = SWZ(off) >> 2;
                g_RT[sw]        = r1p;
                g_RT[2048 + sw] = r2p;
            }
        }
    }
}

// ---------------------------------------------------------------------------
// Kernel 2: fitness via mma.sync bf16 (HMMA; arch-neutral, works on sm_103).
// Grid GRID=592 (one wave @ 4 CTA/SM), block 256.
// Unit = (valid (b,g) item, 128-n tile). D[128,64] = z@R^T via 3 split MMAs
// (z1r1 + z1r2 + z2r1), fp32 register accumulators.
// Warp w owns D rows [16w,16w+16): 4 ksteps x 8 ltiles x 3 mma.m16n8k16.
// ---------------------------------------------------------------------------
__global__ __launch_bounds__(256, 4) void fitness_kernel(
    const int* __restrict__ gidx,
    float*     __restrict__ out)
{
    extern __shared__ char sm[];
    unsigned int smb = smem_u32(sm);
    int tid  = threadIdx.x;
    int wid  = tid >> 5;
    int lane = tid & 31;
    int cta  = blockIdx.x;

    int nunits = 8 * g_nitems;
    int mu = (cta < nunits) ? ((nunits - 1 - cta) / GRID + 1) : 0;
    if (mu == 0) return;

    int*   idxs_s = (int*)(sm + SIDX);
    float* cw_s   = (float*)(sm + SCW);

    // B tiles (r1|r2, 16 KB, pre-swizzled) -> smem once
    {
        const char* src = (const char*)g_RT;
        for (int i = tid; i < 1024; i += 256)
            CP_ASYNC16(smb + SB1 + i * 16, src + i * 16);
        CP_COMMIT();
    }
    CP_WAIT0();

    // ldmatrix lane address components (SW128 on 128B rows:
    // addr = base + row*128 + (kbyte ^ ((row&7)<<4)) )
    unsigned int abase1 = smb + SA1 + (unsigned)(wid * 16 + (lane & 15)) * 128;
    unsigned int abase2 = abase1 + 16384;
    unsigned int axsel  = (unsigned)(lane & 7) << 4;
    unsigned int acol   = (unsigned)(lane >> 4) * 16;
    unsigned int bbase1 = smb + SB1 + (unsigned)(lane & 7) * 128;
    unsigned int bbase2 = bbase1 + 8192;
    unsigned int bcol   = (unsigned)((lane >> 3) & 1) * 16;
    unsigned int bxsel  = (unsigned)(lane & 7) << 4;

    int r    = tid & 127;     // convert: n-row within tile
    int half = tid >> 7;      // convert: k half (32 cols)

    for (int ui = 0; ui < mu; ++ui) {
        int u  = cta + ui * GRID;
        int it = g_items[u >> 3];
        int b  = it >> 8, g = it & 255;
        int n0 = (u & 7) * NTILE;

        __syncthreads();      // prev unit fully consumed (A, cw_s free)
        if (tid < Kn) {
            idxs_s[tid] = __ldg(gidx + (b * Gn + g) * Kn + tid);
            cw_s[tid]   = __ldg(g_cw + (b * Gn + g) * Kn + tid);
        }
        __syncthreads();      // idx/cw visible

        // gather + split-convert + STS.128 (coalesced: warp = 32 consec n)
        {
            const float* zbase = &g_xzT[(size_t)b * Dn * NPn + n0 + r];
            unsigned int sxor = (unsigned)(r & 7) << 4;
            #pragma unroll
            for (int c = 0; c < 4; ++c) {
                int k0 = half * 32 + c * 8;
                unsigned int h4[4], l4[4];
                #pragma unroll
                for (int q = 0; q < 4; ++q) {
                    float f0 = __ldg(zbase + (size_t)idxs_s[k0 + 2*q]     * NPn);
                    float f1 = __ldg(zbase + (size_t)idxs_s[k0 + 2*q + 1] * NPn);
                    unsigned int hp; CVT2(hp, f0, f1);
                    float f0r = f0 - __uint_as_float(hp << 16);
                    float f1r = f1 - __uint_as_float(hp & 0xffff0000u);
                    unsigned int lp; CVT2(lp, f0r, f1r);
                    h4[q] = hp; l4[q] = lp;
                }
                unsigned int off = (unsigned)(r * 128) + (((unsigned)(k0 * 2)) ^ sxor);
                *(uint4*)(sm + SA1 + off) = make_uint4(h4[0], h4[1], h4[2], h4[3]);
                *(uint4*)(sm + SA2 + off) = make_uint4(l4[0], l4[1], l4[2], l4[3]);
            }
        }
        __syncthreads();      // A tiles complete

        // MMA phase
        float d[8][4];
        #pragma unroll
        for (int lt = 0; lt < 8; ++lt)
            #pragma unroll
            for (int q = 0; q < 4; ++q) d[lt][q] = 0.0f;

        #pragma unroll
        for (int ks = 0; ks < 4; ++ks) {
            unsigned int a1[4], a2[4];
            unsigned int ak = ((unsigned)(ks * 32) + acol) ^ axsel;
            LDSM4(a1, abase1 + ak);
            LDSM4(a2, abase2 + ak);
            unsigned int bk = ((unsigned)(ks * 32) + bcol) ^ bxsel;
            #pragma unroll
            for (int lt = 0; lt < 8; ++lt) {
                unsigned int b1r[2], b2r[2];
                LDSM2(b1r, bbase1 + (unsigned)lt * 1024 + bk);
                LDSM2(b2r, bbase2 + (unsigned)lt * 1024 + bk);
                MMA16816(d[lt], a1, b1r);
                MMA16816(d[lt], a1, b2r);
                MMA16816(d[lt], a2, b1r);
            }
        }

        // epilogue: D[row][col]: d0/d1 row=lane>>2, d2/d3 row+8;
        // cols = lt*8 + (lane&3)*2 + {0,1}
        float fs0 = 0.0f, fs1 = 0.0f;
        #pragma unroll
        for (int lt = 0; lt < 8; ++lt) {
            int c0 = lt * 8 + (lane & 3) * 2;
            float cw0 = cw_s[c0], cw1 = cw_s[c0 + 1];
            fs0 += cw0 * d[lt][0] * d[lt][0] + cw1 * d[lt][1] * d[lt][1];
            fs1 += cw0 * d[lt][2] * d[lt][2] + cw1 * d[lt][3] * d[lt][3];
        }
        fs0 += __shfl_xor_sync(0xffffffffu, fs0, 1);
        fs0 += __shfl_xor_sync(0xffffffffu, fs0, 2);
        fs1 += __shfl_xor_sync(0xffffffffu, fs1, 1);
        fs1 += __shfl_xor_sync(0xffffffffu, fs1, 2);
        if ((lane & 3) == 0) {
            int row = n0 + wid * 16 + (lane >> 2);
            atomicAdd(&out[b * NPn + row],     fs0);
            atomicAdd(&out[b * NPn + row + 8], fs1);
        }
    }
}

// ---------------------------------------------------------------------------
// kernel_launch
// Inputs: x, weights, xopt, R, group_indices, valid_mask, group_counts
// ---------------------------------------------------------------------------
extern "C" void kernel_launch(void* const* d_in, const int* in_sizes, int n_in,
                              void* d_out, int out_size)
{
    const float* x      = (const float*)d_in[0];
    const float* w      = (const float*)d_in[1];
    const float* xopt   = (const float*)d_in[2];
    const float* R      = (const float*)d_in[3];
    const int*   gidx   = (const int*)d_in[4];
    const void*  vmask  = (const void*)d_in[5];
    const int*   gc     = (const int*)d_in[6];
    float*       out    = (float*)d_out;

    cudaFuncSetAttribute(fitness_kernel,
                         cudaFuncAttributeMaxDynamicSharedMemorySize, SMEMB);

    dim3 tg(NPn / 32, Dn / 32, Bn);
    prep_kernel<<<tg, dim3(32, 8)>>>(x, xopt, gc, vmask, w, R, out);

    fitness_kernel<<<GRID, 256, SMEMB>>>(gidx, out);
}